// round 12
// baseline (speedup 1.0000x reference)
#include <cuda_runtime.h>
#include <math.h>

#define BQ   1024
#define VN   6890
#define JN   24
#define NBT  10
#define PP   207
#define N3   20670     // VN*3
#define KE   224       // padded K: 207 pose_feature + 10 betas + 7 zeros
#define VPITCH 20736   // padded N (162*128)
#define NJOUT 61       // 24 + 11 + 9 + 17

// ---------------- device scratch (allocation-free) ----------------
__device__ float g_JST[JN * 33];
__device__ float g_pfe[BQ * KE];
__device__ float g_pde[KE * VPITCH];
__device__ float g_vposed[(size_t)BQ * VPITCH];
__device__ __align__(16) float g_A[BQ * JN * 12];

__constant__ int c_parents[24] = {-1,0,0,0,1,2,3,4,5,6,7,8,9,9,9,12,13,14,16,17,18,19,20,21};

// ---------------- packed f32x2 helpers ----------------
__device__ __forceinline__ unsigned long long pack2(float x, float y) {
    unsigned long long r;
    asm("mov.b64 %0, {%1,%2};" : "=l"(r) : "f"(x), "f"(y));
    return r;
}
__device__ __forceinline__ void ffma2(unsigned long long& d, unsigned long long a, unsigned long long b) {
    asm("fma.rn.f32x2 %0, %1, %2, %0;" : "+l"(d) : "l"(a), "l"(b));
}
__device__ __forceinline__ float2 unpack2(unsigned long long v) {
    float2 f;
    asm("mov.b64 {%0,%1}, %2;" : "=f"(f.x), "=f"(f.y) : "l"(v));
    return f;
}

// ---------------- K0a: fold J_regressor (792 blocks, coalesced) ----------------
__global__ void __launch_bounds__(256)
k0_fold(const float* __restrict__ Jreg,
        const float* __restrict__ shapedirs,
        const float* __restrict__ v_template) {
    int j = blockIdx.x / 33, o = blockIdx.x % 33;
    int k = o / 11, l = o % 11;
    int tid = threadIdx.x;
    float acc = 0.f;
    for (int v = tid; v < VN; v += 256) {
        float jr = Jreg[j * VN + v];
        float x  = (l < 10) ? shapedirs[v * 30 + k * 10 + l] : v_template[v * 3 + k];
        acc += jr * x;
    }
    __shared__ float red[256];
    red[tid] = acc;
    __syncthreads();
    #pragma unroll
    for (int s = 128; s >= 32; s >>= 1) {
        if (tid < s) red[tid] += red[tid + s];
        __syncthreads();
    }
    if (tid < 32) {
        float a = red[tid];
        #pragma unroll
        for (int s = 16; s; s >>= 1) a += __shfl_down_sync(0xffffffffu, a, s);
        if (tid == 0) g_JST[j * 33 + k * 11 + l] = a;
    }
}

// ---------------- K0b: build extended B matrix ----------------
__global__ void k0_pde(const float* __restrict__ posedirs,
                       const float* __restrict__ shapedirs) {
    int idx = blockIdx.x * blockDim.x + threadIdx.x;
    int row = idx / VPITCH;
    int col = idx - row * VPITCH;
    float val = 0.f;
    if (col < N3) {
        if (row < PP) {
            val = posedirs[row * N3 + col];
        } else if (row < PP + NBT) {
            int v = col / 3, k = col - v * 3, l = row - PP;
            val = shapedirs[v * 30 + k * 10 + l];
        }
    }
    g_pde[idx] = val;
}

// ---------------- K1: Rodrigues + Jrest + kinematic chain (1 warp/batch) ----------------
__global__ void k1_pose(const float* __restrict__ betas,
                        const float* __restrict__ poses,
                        float* __restrict__ out_joints) {
    int b = blockIdx.x;
    int lane = threadIdx.x;
    __shared__ float sh_b[NBT];
    __shared__ float sh_J[JN * 3];
    __shared__ float sh_T[JN * 12];
    __shared__ float sh_G[JN * 12];

    if (lane < NBT) sh_b[lane] = betas[b * NBT + lane];
    __syncthreads();

    float R[9];
    if (lane < JN) {
        int j = lane;
        float p0 = poses[b * 72 + j * 3 + 0];
        float p1 = poses[b * 72 + j * 3 + 1];
        float p2 = poses[b * 72 + j * 3 + 2];
        const float e = 1e-8f;
        float a0 = p0 + e, a1 = p1 + e, a2 = p2 + e;
        float ang = sqrtf(a0 * a0 + a1 * a1 + a2 * a2);
        float inv = 1.0f / ang;
        float rx = p0 * inv, ry = p1 * inv, rz = p2 * inv;
        float c = cosf(ang), s = sinf(ang), oc = 1.0f - c;
        R[0] = 1.f - oc * (ry * ry + rz * rz);
        R[1] = -s * rz + oc * rx * ry;
        R[2] =  s * ry + oc * rx * rz;
        R[3] =  s * rz + oc * rx * ry;
        R[4] = 1.f - oc * (rx * rx + rz * rz);
        R[5] = -s * rx + oc * ry * rz;
        R[6] = -s * ry + oc * rx * rz;
        R[7] =  s * rx + oc * ry * rz;
        R[8] = 1.f - oc * (rx * rx + ry * ry);

        if (j >= 1) {
            float* pf = &g_pfe[(size_t)b * KE + (j - 1) * 9];
            #pragma unroll
            for (int i = 0; i < 9; i++)
                pf[i] = R[i] - ((i == 0 || i == 4 || i == 8) ? 1.f : 0.f);
        }
        #pragma unroll
        for (int k = 0; k < 3; k++) {
            float acc = g_JST[j * 33 + k * 11 + 10];
            #pragma unroll
            for (int l = 0; l < NBT; l++) acc += sh_b[l] * g_JST[j * 33 + k * 11 + l];
            sh_J[j * 3 + k] = acc;
        }
    }
    if (lane < NBT)               g_pfe[(size_t)b * KE + PP + lane] = sh_b[lane];
    if (lane >= NBT && lane < 17) g_pfe[(size_t)b * KE + PP + lane] = 0.f;
    __syncthreads();

    if (lane < JN) {
        int j = lane;
        float r0 = sh_J[j * 3 + 0], r1 = sh_J[j * 3 + 1], r2 = sh_J[j * 3 + 2];
        if (j > 0) {
            int p = c_parents[j];
            r0 -= sh_J[p * 3 + 0]; r1 -= sh_J[p * 3 + 1]; r2 -= sh_J[p * 3 + 2];
        }
        sh_T[j*12+0]=R[0]; sh_T[j*12+1]=R[1]; sh_T[j*12+ 2]=R[2]; sh_T[j*12+ 3]=r0;
        sh_T[j*12+4]=R[3]; sh_T[j*12+5]=R[4]; sh_T[j*12+ 6]=R[5]; sh_T[j*12+ 7]=r1;
        sh_T[j*12+8]=R[6]; sh_T[j*12+9]=R[7]; sh_T[j*12+10]=R[8]; sh_T[j*12+11]=r2;
    }
    __syncthreads();

    if (lane < 12) sh_G[lane] = sh_T[lane];
    __syncthreads();
    for (int i = 1; i < JN; i++) {
        if (lane < 12) {
            int p = c_parents[i];
            int r = lane >> 2, cc = lane & 3;
            const float* Gp = &sh_G[p * 12 + r * 4];
            const float* Ti = &sh_T[i * 12];
            float v = Gp[0] * Ti[0 * 4 + cc] + Gp[1] * Ti[1 * 4 + cc] + Gp[2] * Ti[2 * 4 + cc];
            if (cc == 3) v += Gp[3];
            sh_G[i * 12 + lane] = v;
        }
        __syncthreads();
    }

    if (lane < JN) {
        int j = lane;
        const float* G = &sh_G[j * 12];
        float j0 = sh_J[j * 3 + 0], j1 = sh_J[j * 3 + 1], j2 = sh_J[j * 3 + 2];
        #pragma unroll
        for (int r = 0; r < 3; r++) {
            size_t base = ((size_t)b * JN + j) * 12 + (size_t)r * 4;
            float g0 = G[r*4+0], g1 = G[r*4+1], g2 = G[r*4+2], g3 = G[r*4+3];
            g_A[base + 0] = g0;
            g_A[base + 1] = g1;
            g_A[base + 2] = g2;
            g_A[base + 3] = g3 - (g0 * j0 + g1 * j1 + g2 * j2);
            out_joints[((size_t)b * NJOUT + j) * 3 + r] = g3;
        }
    }
}

// ---------------- tf32 helpers ----------------
__device__ __forceinline__ unsigned f2tf32(float f) {
    unsigned r;
    asm("cvt.rna.tf32.f32 %0, %1;" : "=r"(r) : "f"(f));
    return r;
}
__device__ __forceinline__ void mma_tf32(float* d, const unsigned* a, const unsigned* b) {
    asm("mma.sync.aligned.m16n8k8.row.col.f32.tf32.tf32.f32 "
        "{%0,%1,%2,%3}, {%4,%5,%6,%7}, {%8,%9}, {%0,%1,%2,%3};"
        : "+f"(d[0]), "+f"(d[1]), "+f"(d[2]), "+f"(d[3])
        : "r"(a[0]), "r"(a[1]), "r"(a[2]), "r"(a[3]), "r"(b[0]), "r"(b[1]));
}

// ---------------- K2: tf32 tensor-core GEMM 128x128x32 (known-good) ----------------
#define ASTRIDE 36
#define BSTRIDE 136

__global__ void __launch_bounds__(256)
k2_gemm(const float* __restrict__ v_template) {
    __shared__ unsigned As[128 * ASTRIDE];
    __shared__ unsigned Bs[32 * BSTRIDE];

    int tid  = threadIdx.x;
    int wid  = tid >> 5, lane = tid & 31;
    int gid  = lane >> 2, tig = lane & 3;
    int wm   = wid & 1;
    int wn   = wid >> 1;
    int m0   = blockIdx.y * 128;
    int n0   = blockIdx.x * 128;

    int aRow = tid >> 3, aCol = (tid & 7) * 4;
    int bRow = tid >> 5, bCol = (tid & 31) * 4;

    float acc[4][4][4];
    #pragma unroll
    for (int i = 0; i < 4; i++)
        #pragma unroll
        for (int j = 0; j < 4; j++)
            #pragma unroll
            for (int r = 0; r < 4; r++) acc[i][j][r] = 0.f;

    float4 ra[4], rb[4];
    #pragma unroll
    for (int i = 0; i < 4; i++) {
        ra[i] = *(const float4*)&g_pfe[(size_t)(m0 + aRow + i * 32) * KE + aCol];
        rb[i] = *(const float4*)&g_pde[(size_t)(bRow + i * 8) * VPITCH + n0 + bCol];
    }

    for (int kt = 0; kt < KE; kt += 32) {
        #pragma unroll
        for (int i = 0; i < 4; i++) {
            unsigned* pa = &As[(aRow + i * 32) * ASTRIDE + aCol];
            pa[0] = f2tf32(ra[i].x); pa[1] = f2tf32(ra[i].y);
            pa[2] = f2tf32(ra[i].z); pa[3] = f2tf32(ra[i].w);
            unsigned* pb = &Bs[(bRow + i * 8) * BSTRIDE + bCol];
            pb[0] = f2tf32(rb[i].x); pb[1] = f2tf32(rb[i].y);
            pb[2] = f2tf32(rb[i].z); pb[3] = f2tf32(rb[i].w);
        }
        __syncthreads();

        if (kt + 32 < KE) {
            #pragma unroll
            for (int i = 0; i < 4; i++) {
                ra[i] = *(const float4*)&g_pfe[(size_t)(m0 + aRow + i * 32) * KE + kt + 32 + aCol];
                rb[i] = *(const float4*)&g_pde[(size_t)(kt + 32 + bRow + i * 8) * VPITCH + n0 + bCol];
            }
        }

        #pragma unroll
        for (int ks = 0; ks < 4; ks++) {
            int k0 = ks * 8;
            unsigned af[4][4], bf[4][2];
            #pragma unroll
            for (int mt = 0; mt < 4; mt++) {
                int r = wm * 64 + mt * 16 + gid;
                af[mt][0] = As[(r)     * ASTRIDE + k0 + tig];
                af[mt][1] = As[(r + 8) * ASTRIDE + k0 + tig];
                af[mt][2] = As[(r)     * ASTRIDE + k0 + tig + 4];
                af[mt][3] = As[(r + 8) * ASTRIDE + k0 + tig + 4];
            }
            #pragma unroll
            for (int nt = 0; nt < 4; nt++) {
                int n = wn * 32 + nt * 8 + gid;
                bf[nt][0] = Bs[(k0 + tig)     * BSTRIDE + n];
                bf[nt][1] = Bs[(k0 + tig + 4) * BSTRIDE + n];
            }
            #pragma unroll
            for (int mt = 0; mt < 4; mt++)
                #pragma unroll
                for (int nt = 0; nt < 4; nt++)
                    mma_tf32(acc[mt][nt], af[mt], bf[nt]);
        }
        __syncthreads();
    }

    #pragma unroll
    for (int mt = 0; mt < 4; mt++) {
        int m = m0 + wm * 64 + mt * 16 + gid;
        #pragma unroll
        for (int nt = 0; nt < 4; nt++) {
            int n = n0 + wn * 32 + nt * 8 + 2 * tig;
            float b0v = (n     < N3) ? v_template[n]     : 0.f;
            float b1v = (n + 1 < N3) ? v_template[n + 1] : 0.f;
            float2 lo = make_float2(acc[mt][nt][0] + b0v, acc[mt][nt][1] + b1v);
            float2 hi = make_float2(acc[mt][nt][2] + b0v, acc[mt][nt][3] + b1v);
            *(float2*)&g_vposed[(size_t)m       * VPITCH + n] = lo;
            *(float2*)&g_vposed[(size_t)(m + 8) * VPITCH + n] = hi;
        }
    }
}

// ---------------- K3: skinning with packed f32x2, 4 batches/block (R10 known-good) ----------------
#define NBPB 4
__global__ void __launch_bounds__(256)
k3_skin(const float* __restrict__ lbs_weights,
        float* __restrict__ out_verts) {
    __shared__ ulonglong2 sA2[NBPB][JN * 3];
    int b0 = blockIdx.y * NBPB;
    int tid = threadIdx.x;
    const ulonglong2* gA2 = (const ulonglong2*)g_A;
    for (int i = tid; i < NBPB * JN * 3; i += 256) {
        int bb = i / (JN * 3), r = i - bb * (JN * 3);
        sA2[bb][r] = gA2[(size_t)(b0 + bb) * (JN * 3) + r];
    }
    __syncthreads();

    int v = blockIdx.x * 256 + tid;
    if (v >= VN) return;

    unsigned long long wd[JN];
    const float4* wp = (const float4*)&lbs_weights[(size_t)v * JN];
    #pragma unroll
    for (int q = 0; q < 6; q++) {
        float4 t = wp[q];
        wd[q * 4 + 0] = pack2(t.x, t.x);
        wd[q * 4 + 1] = pack2(t.y, t.y);
        wd[q * 4 + 2] = pack2(t.z, t.z);
        wd[q * 4 + 3] = pack2(t.w, t.w);
    }

    #pragma unroll
    for (int bb = 0; bb < NBPB; bb++) {
        unsigned long long T[6];
        #pragma unroll
        for (int r = 0; r < 6; r++) T[r] = 0ULL;
        #pragma unroll
        for (int j = 0; j < JN; j++) {
            ulonglong2 q0 = sA2[bb][j * 3 + 0];
            ulonglong2 q1 = sA2[bb][j * 3 + 1];
            ulonglong2 q2 = sA2[bb][j * 3 + 2];
            ffma2(T[0], wd[j], q0.x); ffma2(T[1], wd[j], q0.y);
            ffma2(T[2], wd[j], q1.x); ffma2(T[3], wd[j], q1.y);
            ffma2(T[4], wd[j], q2.x); ffma2(T[5], wd[j], q2.y);
        }
        float2 t0 = unpack2(T[0]), t1 = unpack2(T[1]), t2 = unpack2(T[2]);
        float2 t3 = unpack2(T[3]), t4 = unpack2(T[4]), t5 = unpack2(T[5]);
        int b = b0 + bb;
        size_t vb = (size_t)b * VPITCH + (size_t)v * 3;
        float vx = g_vposed[vb + 0], vy = g_vposed[vb + 1], vz = g_vposed[vb + 2];
        float ox = t0.x * vx + t0.y * vy + t1.x * vz + t1.y;
        float oy = t2.x * vx + t2.y * vy + t3.x * vz + t3.y;
        float oz = t4.x * vx + t4.y * vy + t5.x * vz + t5.y;
        size_t ob = ((size_t)b * VN + v) * 3;
        out_verts[ob + 0] = ox;
        out_verts[ob + 1] = oy;
        out_verts[ob + 2] = oz;
    }
}

// ---------------- K4: joint regression with smem-tiled regressor (R10 known-good) ----------------
#define K4B 4
#define CH  256
#define CHP 257
__global__ void __launch_bounds__(256)
k4_reg(const float* __restrict__ Je9,
       const float* __restrict__ Jh17,
       const float* __restrict__ verts,
       float* __restrict__ out_joints) {
    __shared__ float sJr[26 * CHP];
    __shared__ float sv[K4B][CH * 3];
    __shared__ float red[K4B][240];
    int b0 = blockIdx.x * K4B;
    int tid = threadIdx.x;

    int p = tid / 3;
    int s = tid - p * 3;
    int jj = p / 3, k = p - jj * 3;

    float acc[K4B];
    #pragma unroll
    for (int bb = 0; bb < K4B; bb++) acc[bb] = 0.f;

    for (int v0 = 0; v0 < VN; v0 += CH) {
        int cnt = VN - v0; if (cnt > CH) cnt = CH;
        for (int i = tid; i < 26 * cnt; i += 256) {
            int rj = i / cnt;
            int v  = i - rj * cnt;
            float val = (rj < 9) ? Je9[(size_t)rj * VN + v0 + v]
                                 : Jh17[(size_t)(rj - 9) * VN + v0 + v];
            sJr[rj * CHP + v] = val;
        }
        int n2 = (cnt * 3) / 2;
        #pragma unroll
        for (int bb = 0; bb < K4B; bb++) {
            const float* src = &verts[((size_t)(b0 + bb) * VN + v0) * 3];
            float2* dst2 = (float2*)&sv[bb][0];
            const float2* src2 = (const float2*)src;
            for (int i = tid; i < n2; i += 256)
                dst2[i] = src2[i];
            for (int i = n2 * 2 + tid; i < cnt * 3; i += 256)
                sv[bb][i] = src[i];
        }
        __syncthreads();
        if (tid < 234) {
            for (int v = s; v < cnt; v += 3) {
                float jr = sJr[jj * CHP + v];
                #pragma unroll
                for (int bb = 0; bb < K4B; bb++)
                    acc[bb] += jr * sv[bb][v * 3 + k];
            }
        }
        __syncthreads();
    }
    if (tid < 234) {
        #pragma unroll
        for (int bb = 0; bb < K4B; bb++) red[bb][tid] = acc[bb];
    }
    __syncthreads();
    if (tid < 78) {
        int jjo = tid / 3, ko = tid - jjo * 3;
        #pragma unroll
        for (int bb = 0; bb < K4B; bb++) {
            float total = red[bb][tid * 3] + red[bb][tid * 3 + 1] + red[bb][tid * 3 + 2];
            out_joints[((size_t)(b0 + bb) * NJOUT + 35 + jjo) * 3 + ko] = total;
        }
    }
}

// ---------------- K5: extra11 gather ----------------
__global__ void k5_gather(const int* __restrict__ idxs,
                          const float* __restrict__ verts,
                          float* __restrict__ out_joints) {
    int t = blockIdx.x * blockDim.x + threadIdx.x;
    int b = t / 33;
    int r = t - b * 33;
    int i = r / 3, k = r % 3;
    int v = idxs[i];
    out_joints[((size_t)b * NJOUT + 24 + i) * 3 + k] = verts[((size_t)b * VN + v) * 3 + k];
}

// ---------------- launch ----------------
// ATTRIBUTION ROUND: k3_skin is launched 3x (idempotent — same inputs, same
// outputs). k3_cost = (total_dur - 538.6us) / 2. Correctness unaffected.
extern "C" void kernel_launch(void* const* d_in, const int* in_sizes, int n_in,
                              void* d_out, int out_size) {
    (void)in_sizes; (void)n_in; (void)out_size;
    const float* betas      = (const float*)d_in[0];
    const float* poses      = (const float*)d_in[1];
    const int*   ext_idx    = (const int*)  d_in[2];
    const float* v_template = (const float*)d_in[3];
    const float* shapedirs  = (const float*)d_in[4];
    const float* posedirs   = (const float*)d_in[5];
    const float* Jreg       = (const float*)d_in[6];
    const float* lbs_w      = (const float*)d_in[7];
    const float* Je9        = (const float*)d_in[8];
    const float* Jh17       = (const float*)d_in[9];

    float* out_verts  = (float*)d_out;
    float* out_joints = out_verts + (size_t)BQ * VN * 3;

    k0_fold<<<JN * 33, 256>>>(Jreg, shapedirs, v_template);
    k0_pde<<<(KE * VPITCH) / 256, 256>>>(posedirs, shapedirs);
    k1_pose<<<BQ, 32>>>(betas, poses, out_joints);
    k2_gemm<<<dim3(VPITCH / 128, BQ / 128), 256>>>(v_template);
    k3_skin<<<dim3((VN + 255) / 256, BQ / NBPB), 256>>>(lbs_w, out_verts);
    k3_skin<<<dim3((VN + 255) / 256, BQ / NBPB), 256>>>(lbs_w, out_verts);  // dup #1 (measurement)
    k3_skin<<<dim3((VN + 255) / 256, BQ / NBPB), 256>>>(lbs_w, out_verts);  // dup #2 (measurement)
    k4_reg<<<BQ / K4B, 256>>>(Je9, Jh17, out_verts, out_joints);
    k5_gather<<<(BQ * 11 * 3) / 256, 256>>>(ext_idx, out_verts, out_joints);
}

// round 13
// speedup vs baseline: 1.5389x; 1.5389x over previous
#include <cuda_runtime.h>
#include <math.h>

#define BQ   1024
#define VN   6890
#define JN   24
#define NBT  10
#define PP   207
#define N3   20670     // VN*3
#define KE   224       // padded K: 207 pose_feature + 10 betas + 7 zeros
#define VPITCH 20736   // padded N (162*128)
#define NJOUT 61       // 24 + 11 + 9 + 17

// ---------------- device scratch (allocation-free) ----------------
__device__ float g_JST[JN * 33];
__device__ float g_pfe[BQ * KE];
__device__ float g_pde[KE * VPITCH];
__device__ float g_vposed[(size_t)BQ * VPITCH];
__device__ __align__(16) float g_A[BQ * JN * 12];

__constant__ int c_parents[24] = {-1,0,0,0,1,2,3,4,5,6,7,8,9,9,9,12,13,14,16,17,18,19,20,21};

// ---------------- packed f32x2 helpers ----------------
__device__ __forceinline__ unsigned long long pack2(float x, float y) {
    unsigned long long r;
    asm("mov.b64 %0, {%1,%2};" : "=l"(r) : "f"(x), "f"(y));
    return r;
}
__device__ __forceinline__ void ffma2(unsigned long long& d, unsigned long long a, unsigned long long b) {
    asm("fma.rn.f32x2 %0, %1, %2, %0;" : "+l"(d) : "l"(a), "l"(b));
}
__device__ __forceinline__ float2 unpack2(unsigned long long v) {
    float2 f;
    asm("mov.b64 {%0,%1}, %2;" : "=f"(f.x), "=f"(f.y) : "l"(v));
    return f;
}

// ---------------- K0a: fold J_regressor (792 blocks, coalesced) ----------------
__global__ void __launch_bounds__(256)
k0_fold(const float* __restrict__ Jreg,
        const float* __restrict__ shapedirs,
        const float* __restrict__ v_template) {
    int j = blockIdx.x / 33, o = blockIdx.x % 33;
    int k = o / 11, l = o % 11;
    int tid = threadIdx.x;
    float acc = 0.f;
    for (int v = tid; v < VN; v += 256) {
        float jr = Jreg[j * VN + v];
        float x  = (l < 10) ? shapedirs[v * 30 + k * 10 + l] : v_template[v * 3 + k];
        acc += jr * x;
    }
    __shared__ float red[256];
    red[tid] = acc;
    __syncthreads();
    #pragma unroll
    for (int s = 128; s >= 32; s >>= 1) {
        if (tid < s) red[tid] += red[tid + s];
        __syncthreads();
    }
    if (tid < 32) {
        float a = red[tid];
        #pragma unroll
        for (int s = 16; s; s >>= 1) a += __shfl_down_sync(0xffffffffu, a, s);
        if (tid == 0) g_JST[j * 33 + k * 11 + l] = a;
    }
}

// ---------------- K0b: build extended B matrix ----------------
__global__ void k0_pde(const float* __restrict__ posedirs,
                       const float* __restrict__ shapedirs) {
    int idx = blockIdx.x * blockDim.x + threadIdx.x;
    int row = idx / VPITCH;
    int col = idx - row * VPITCH;
    float val = 0.f;
    if (col < N3) {
        if (row < PP) {
            val = posedirs[row * N3 + col];
        } else if (row < PP + NBT) {
            int v = col / 3, k = col - v * 3, l = row - PP;
            val = shapedirs[v * 30 + k * 10 + l];
        }
    }
    g_pde[idx] = val;
}

// ---------------- K1: Rodrigues + Jrest + kinematic chain (1 warp/batch) ----------------
__global__ void k1_pose(const float* __restrict__ betas,
                        const float* __restrict__ poses,
                        float* __restrict__ out_joints) {
    int b = blockIdx.x;
    int lane = threadIdx.x;
    __shared__ float sh_b[NBT];
    __shared__ float sh_J[JN * 3];
    __shared__ float sh_T[JN * 12];
    __shared__ float sh_G[JN * 12];

    if (lane < NBT) sh_b[lane] = betas[b * NBT + lane];
    __syncthreads();

    float R[9];
    if (lane < JN) {
        int j = lane;
        float p0 = poses[b * 72 + j * 3 + 0];
        float p1 = poses[b * 72 + j * 3 + 1];
        float p2 = poses[b * 72 + j * 3 + 2];
        const float e = 1e-8f;
        float a0 = p0 + e, a1 = p1 + e, a2 = p2 + e;
        float ang = sqrtf(a0 * a0 + a1 * a1 + a2 * a2);
        float inv = 1.0f / ang;
        float rx = p0 * inv, ry = p1 * inv, rz = p2 * inv;
        float c = cosf(ang), s = sinf(ang), oc = 1.0f - c;
        R[0] = 1.f - oc * (ry * ry + rz * rz);
        R[1] = -s * rz + oc * rx * ry;
        R[2] =  s * ry + oc * rx * rz;
        R[3] =  s * rz + oc * rx * ry;
        R[4] = 1.f - oc * (rx * rx + rz * rz);
        R[5] = -s * rx + oc * ry * rz;
        R[6] = -s * ry + oc * rx * rz;
        R[7] =  s * rx + oc * ry * rz;
        R[8] = 1.f - oc * (rx * rx + ry * ry);

        if (j >= 1) {
            float* pf = &g_pfe[(size_t)b * KE + (j - 1) * 9];
            #pragma unroll
            for (int i = 0; i < 9; i++)
                pf[i] = R[i] - ((i == 0 || i == 4 || i == 8) ? 1.f : 0.f);
        }
        #pragma unroll
        for (int k = 0; k < 3; k++) {
            float acc = g_JST[j * 33 + k * 11 + 10];
            #pragma unroll
            for (int l = 0; l < NBT; l++) acc += sh_b[l] * g_JST[j * 33 + k * 11 + l];
            sh_J[j * 3 + k] = acc;
        }
    }
    if (lane < NBT)               g_pfe[(size_t)b * KE + PP + lane] = sh_b[lane];
    if (lane >= NBT && lane < 17) g_pfe[(size_t)b * KE + PP + lane] = 0.f;
    __syncthreads();

    if (lane < JN) {
        int j = lane;
        float r0 = sh_J[j * 3 + 0], r1 = sh_J[j * 3 + 1], r2 = sh_J[j * 3 + 2];
        if (j > 0) {
            int p = c_parents[j];
            r0 -= sh_J[p * 3 + 0]; r1 -= sh_J[p * 3 + 1]; r2 -= sh_J[p * 3 + 2];
        }
        sh_T[j*12+0]=R[0]; sh_T[j*12+1]=R[1]; sh_T[j*12+ 2]=R[2]; sh_T[j*12+ 3]=r0;
        sh_T[j*12+4]=R[3]; sh_T[j*12+5]=R[4]; sh_T[j*12+ 6]=R[5]; sh_T[j*12+ 7]=r1;
        sh_T[j*12+8]=R[6]; sh_T[j*12+9]=R[7]; sh_T[j*12+10]=R[8]; sh_T[j*12+11]=r2;
    }
    __syncthreads();

    if (lane < 12) sh_G[lane] = sh_T[lane];
    __syncthreads();
    for (int i = 1; i < JN; i++) {
        if (lane < 12) {
            int p = c_parents[i];
            int r = lane >> 2, cc = lane & 3;
            const float* Gp = &sh_G[p * 12 + r * 4];
            const float* Ti = &sh_T[i * 12];
            float v = Gp[0] * Ti[0 * 4 + cc] + Gp[1] * Ti[1 * 4 + cc] + Gp[2] * Ti[2 * 4 + cc];
            if (cc == 3) v += Gp[3];
            sh_G[i * 12 + lane] = v;
        }
        __syncthreads();
    }

    if (lane < JN) {
        int j = lane;
        const float* G = &sh_G[j * 12];
        float j0 = sh_J[j * 3 + 0], j1 = sh_J[j * 3 + 1], j2 = sh_J[j * 3 + 2];
        #pragma unroll
        for (int r = 0; r < 3; r++) {
            size_t base = ((size_t)b * JN + j) * 12 + (size_t)r * 4;
            float g0 = G[r*4+0], g1 = G[r*4+1], g2 = G[r*4+2], g3 = G[r*4+3];
            g_A[base + 0] = g0;
            g_A[base + 1] = g1;
            g_A[base + 2] = g2;
            g_A[base + 3] = g3 - (g0 * j0 + g1 * j1 + g2 * j2);
            out_joints[((size_t)b * NJOUT + j) * 3 + r] = g3;
        }
    }
}

// ---------------- tf32 helpers ----------------
__device__ __forceinline__ unsigned f2tf32(float f) {
    unsigned r;
    asm("cvt.rna.tf32.f32 %0, %1;" : "=r"(r) : "f"(f));
    return r;
}
__device__ __forceinline__ void mma_tf32(float* d, const unsigned* a, const unsigned* b) {
    asm("mma.sync.aligned.m16n8k8.row.col.f32.tf32.tf32.f32 "
        "{%0,%1,%2,%3}, {%4,%5,%6,%7}, {%8,%9}, {%0,%1,%2,%3};"
        : "+f"(d[0]), "+f"(d[1]), "+f"(d[2]), "+f"(d[3])
        : "r"(a[0]), "r"(a[1]), "r"(a[2]), "r"(a[3]), "r"(b[0]), "r"(b[1]));
}

// ---------------- K2: tf32 tensor-core GEMM 128x128x32 (known-good) ----------------
#define ASTRIDE 36
#define BSTRIDE 136

__global__ void __launch_bounds__(256)
k2_gemm(const float* __restrict__ v_template) {
    __shared__ unsigned As[128 * ASTRIDE];
    __shared__ unsigned Bs[32 * BSTRIDE];

    int tid  = threadIdx.x;
    int wid  = tid >> 5, lane = tid & 31;
    int gid  = lane >> 2, tig = lane & 3;
    int wm   = wid & 1;
    int wn   = wid >> 1;
    int m0   = blockIdx.y * 128;
    int n0   = blockIdx.x * 128;

    int aRow = tid >> 3, aCol = (tid & 7) * 4;
    int bRow = tid >> 5, bCol = (tid & 31) * 4;

    float acc[4][4][4];
    #pragma unroll
    for (int i = 0; i < 4; i++)
        #pragma unroll
        for (int j = 0; j < 4; j++)
            #pragma unroll
            for (int r = 0; r < 4; r++) acc[i][j][r] = 0.f;

    float4 ra[4], rb[4];
    #pragma unroll
    for (int i = 0; i < 4; i++) {
        ra[i] = *(const float4*)&g_pfe[(size_t)(m0 + aRow + i * 32) * KE + aCol];
        rb[i] = *(const float4*)&g_pde[(size_t)(bRow + i * 8) * VPITCH + n0 + bCol];
    }

    for (int kt = 0; kt < KE; kt += 32) {
        #pragma unroll
        for (int i = 0; i < 4; i++) {
            unsigned* pa = &As[(aRow + i * 32) * ASTRIDE + aCol];
            pa[0] = f2tf32(ra[i].x); pa[1] = f2tf32(ra[i].y);
            pa[2] = f2tf32(ra[i].z); pa[3] = f2tf32(ra[i].w);
            unsigned* pb = &Bs[(bRow + i * 8) * BSTRIDE + bCol];
            pb[0] = f2tf32(rb[i].x); pb[1] = f2tf32(rb[i].y);
            pb[2] = f2tf32(rb[i].z); pb[3] = f2tf32(rb[i].w);
        }
        __syncthreads();

        if (kt + 32 < KE) {
            #pragma unroll
            for (int i = 0; i < 4; i++) {
                ra[i] = *(const float4*)&g_pfe[(size_t)(m0 + aRow + i * 32) * KE + kt + 32 + aCol];
                rb[i] = *(const float4*)&g_pde[(size_t)(kt + 32 + bRow + i * 8) * VPITCH + n0 + bCol];
            }
        }

        #pragma unroll
        for (int ks = 0; ks < 4; ks++) {
            int k0 = ks * 8;
            unsigned af[4][4], bf[4][2];
            #pragma unroll
            for (int mt = 0; mt < 4; mt++) {
                int r = wm * 64 + mt * 16 + gid;
                af[mt][0] = As[(r)     * ASTRIDE + k0 + tig];
                af[mt][1] = As[(r + 8) * ASTRIDE + k0 + tig];
                af[mt][2] = As[(r)     * ASTRIDE + k0 + tig + 4];
                af[mt][3] = As[(r + 8) * ASTRIDE + k0 + tig + 4];
            }
            #pragma unroll
            for (int nt = 0; nt < 4; nt++) {
                int n = wn * 32 + nt * 8 + gid;
                bf[nt][0] = Bs[(k0 + tig)     * BSTRIDE + n];
                bf[nt][1] = Bs[(k0 + tig + 4) * BSTRIDE + n];
            }
            #pragma unroll
            for (int mt = 0; mt < 4; mt++)
                #pragma unroll
                for (int nt = 0; nt < 4; nt++)
                    mma_tf32(acc[mt][nt], af[mt], bf[nt]);
        }
        __syncthreads();
    }

    #pragma unroll
    for (int mt = 0; mt < 4; mt++) {
        int m = m0 + wm * 64 + mt * 16 + gid;
        #pragma unroll
        for (int nt = 0; nt < 4; nt++) {
            int n = n0 + wn * 32 + nt * 8 + 2 * tig;
            float b0v = (n     < N3) ? v_template[n]     : 0.f;
            float b1v = (n + 1 < N3) ? v_template[n + 1] : 0.f;
            float2 lo = make_float2(acc[mt][nt][0] + b0v, acc[mt][nt][1] + b1v);
            float2 hi = make_float2(acc[mt][nt][2] + b0v, acc[mt][nt][3] + b1v);
            *(float2*)&g_vposed[(size_t)m       * VPITCH + n] = lo;
            *(float2*)&g_vposed[(size_t)(m + 8) * VPITCH + n] = hi;
        }
    }
}

// ---------------- K3: skinning with packed f32x2, 4 batches/block (known-good, 137us) ----------------
#define NBPB 4
__global__ void __launch_bounds__(256)
k3_skin(const float* __restrict__ lbs_weights,
        float* __restrict__ out_verts) {
    __shared__ ulonglong2 sA2[NBPB][JN * 3];
    int b0 = blockIdx.y * NBPB;
    int tid = threadIdx.x;
    const ulonglong2* gA2 = (const ulonglong2*)g_A;
    for (int i = tid; i < NBPB * JN * 3; i += 256) {
        int bb = i / (JN * 3), r = i - bb * (JN * 3);
        sA2[bb][r] = gA2[(size_t)(b0 + bb) * (JN * 3) + r];
    }
    __syncthreads();

    int v = blockIdx.x * 256 + tid;
    if (v >= VN) return;

    unsigned long long wd[JN];
    const float4* wp = (const float4*)&lbs_weights[(size_t)v * JN];
    #pragma unroll
    for (int q = 0; q < 6; q++) {
        float4 t = wp[q];
        wd[q * 4 + 0] = pack2(t.x, t.x);
        wd[q * 4 + 1] = pack2(t.y, t.y);
        wd[q * 4 + 2] = pack2(t.z, t.z);
        wd[q * 4 + 3] = pack2(t.w, t.w);
    }

    #pragma unroll
    for (int bb = 0; bb < NBPB; bb++) {
        unsigned long long T[6];
        #pragma unroll
        for (int r = 0; r < 6; r++) T[r] = 0ULL;
        #pragma unroll
        for (int j = 0; j < JN; j++) {
            ulonglong2 q0 = sA2[bb][j * 3 + 0];
            ulonglong2 q1 = sA2[bb][j * 3 + 1];
            ulonglong2 q2 = sA2[bb][j * 3 + 2];
            ffma2(T[0], wd[j], q0.x); ffma2(T[1], wd[j], q0.y);
            ffma2(T[2], wd[j], q1.x); ffma2(T[3], wd[j], q1.y);
            ffma2(T[4], wd[j], q2.x); ffma2(T[5], wd[j], q2.y);
        }
        float2 t0 = unpack2(T[0]), t1 = unpack2(T[1]), t2 = unpack2(T[2]);
        float2 t3 = unpack2(T[3]), t4 = unpack2(T[4]), t5 = unpack2(T[5]);
        int b = b0 + bb;
        size_t vb = (size_t)b * VPITCH + (size_t)v * 3;
        float vx = g_vposed[vb + 0], vy = g_vposed[vb + 1], vz = g_vposed[vb + 2];
        float ox = t0.x * vx + t0.y * vy + t1.x * vz + t1.y;
        float oy = t2.x * vx + t2.y * vy + t3.x * vz + t3.y;
        float oz = t4.x * vx + t4.y * vy + t5.x * vz + t5.y;
        size_t ob = ((size_t)b * VN + v) * 3;
        out_verts[ob + 0] = ox;
        out_verts[ob + 1] = oy;
        out_verts[ob + 2] = oz;
    }
}

// ---------------- K4: joint regression, warp-per-rows mapping ----------------
// Warp w accumulates rows {w, w+8, w+16} (+ {w+24} for w<2) across all 3 comps
// and 4 batches in registers; lanes stride v by 32; butterfly-reduce at end.
#define K4B 4
#define CH  256
#define CHP 257

#define K4_BODY(vi)                                                        \
    {                                                                      \
        float jr0 = sJr[(w)      * CHP + (vi)];                            \
        float jr1 = sJr[(w + 8)  * CHP + (vi)];                            \
        float jr2 = sJr[(w + 16) * CHP + (vi)];                            \
        float jr3 = (w < 2) ? sJr[(w + 24) * CHP + (vi)] : 0.f;            \
        _Pragma("unroll")                                                  \
        for (int bb = 0; bb < K4B; bb++) {                                 \
            float vx = sv[bb][(vi) * 3 + 0];                               \
            float vy = sv[bb][(vi) * 3 + 1];                               \
            float vz = sv[bb][(vi) * 3 + 2];                               \
            acc[0][0][bb] += jr0 * vx; acc[0][1][bb] += jr0 * vy; acc[0][2][bb] += jr0 * vz; \
            acc[1][0][bb] += jr1 * vx; acc[1][1][bb] += jr1 * vy; acc[1][2][bb] += jr1 * vz; \
            acc[2][0][bb] += jr2 * vx; acc[2][1][bb] += jr2 * vy; acc[2][2][bb] += jr2 * vz; \
            acc[3][0][bb] += jr3 * vx; acc[3][1][bb] += jr3 * vy; acc[3][2][bb] += jr3 * vz; \
        }                                                                  \
    }

__global__ void __launch_bounds__(256)
k4_reg(const float* __restrict__ Je9,
       const float* __restrict__ Jh17,
       const float* __restrict__ verts,
       float* __restrict__ out_joints) {
    __shared__ float sJr[26 * CHP];
    __shared__ float sv[K4B][CH * 3];
    int b0 = blockIdx.x * K4B;
    int tid = threadIdx.x;
    int w = tid >> 5, lane = tid & 31;

    float acc[4][3][K4B];
    #pragma unroll
    for (int r = 0; r < 4; r++)
        #pragma unroll
        for (int k = 0; k < 3; k++)
            #pragma unroll
            for (int bb = 0; bb < K4B; bb++) acc[r][k][bb] = 0.f;

    for (int v0 = 0; v0 < VN; v0 += CH) {
        int cnt = VN - v0; if (cnt > CH) cnt = CH;
        // stage regressor rows, coalesced
        for (int i = tid; i < 26 * cnt; i += 256) {
            int rj = i / cnt;
            int v  = i - rj * cnt;
            float val = (rj < 9) ? Je9[(size_t)rj * VN + v0 + v]
                                 : Jh17[(size_t)(rj - 9) * VN + v0 + v];
            sJr[rj * CHP + v] = val;
        }
        // stage vertices (float2: batch base is 8B-aligned)
        int n2 = (cnt * 3) / 2;
        #pragma unroll
        for (int bb = 0; bb < K4B; bb++) {
            const float* src = &verts[((size_t)(b0 + bb) * VN + v0) * 3];
            float2* dst2 = (float2*)&sv[bb][0];
            const float2* src2 = (const float2*)src;
            for (int i = tid; i < n2; i += 256)
                dst2[i] = src2[i];
            for (int i = n2 * 2 + tid; i < cnt * 3; i += 256)
                sv[bb][i] = src[i];
        }
        __syncthreads();

        if (cnt == CH) {
            #pragma unroll
            for (int it = 0; it < CH / 32; it++)
                K4_BODY(lane + it * 32)
        } else {
            for (int vi = lane; vi < cnt; vi += 32)
                K4_BODY(vi)
        }
        __syncthreads();
    }

    // butterfly reduce across lanes
    #pragma unroll
    for (int r = 0; r < 4; r++)
        #pragma unroll
        for (int k = 0; k < 3; k++)
            #pragma unroll
            for (int bb = 0; bb < K4B; bb++) {
                float s = acc[r][k][bb];
                #pragma unroll
                for (int off = 16; off; off >>= 1)
                    s += __shfl_xor_sync(0xffffffffu, s, off);
                acc[r][k][bb] = s;
            }

    if (lane == 0) {
        int nrows = (w < 2) ? 4 : 3;
        #pragma unroll
        for (int r = 0; r < 4; r++) {
            if (r < nrows) {
                int row = w + r * 8;      // w, w+8, w+16, w+24
                #pragma unroll
                for (int bb = 0; bb < K4B; bb++) {
                    size_t base = ((size_t)(b0 + bb) * NJOUT + 35 + row) * 3;
                    out_joints[base + 0] = acc[r][0][bb];
                    out_joints[base + 1] = acc[r][1][bb];
                    out_joints[base + 2] = acc[r][2][bb];
                }
            }
        }
    }
}

// ---------------- K5: extra11 gather ----------------
__global__ void k5_gather(const int* __restrict__ idxs,
                          const float* __restrict__ verts,
                          float* __restrict__ out_joints) {
    int t = blockIdx.x * blockDim.x + threadIdx.x;
    int b = t / 33;
    int r = t - b * 33;
    int i = r / 3, k = r % 3;
    int v = idxs[i];
    out_joints[((size_t)b * NJOUT + 24 + i) * 3 + k] = verts[((size_t)b * VN + v) * 3 + k];
}

// ---------------- launch ----------------
extern "C" void kernel_launch(void* const* d_in, const int* in_sizes, int n_in,
                              void* d_out, int out_size) {
    (void)in_sizes; (void)n_in; (void)out_size;
    const float* betas      = (const float*)d_in[0];
    const float* poses      = (const float*)d_in[1];
    const int*   ext_idx    = (const int*)  d_in[2];
    const float* v_template = (const float*)d_in[3];
    const float* shapedirs  = (const float*)d_in[4];
    const float* posedirs   = (const float*)d_in[5];
    const float* Jreg       = (const float*)d_in[6];
    const float* lbs_w      = (const float*)d_in[7];
    const float* Je9        = (const float*)d_in[8];
    const float* Jh17       = (const float*)d_in[9];

    float* out_verts  = (float*)d_out;
    float* out_joints = out_verts + (size_t)BQ * VN * 3;

    k0_fold<<<JN * 33, 256>>>(Jreg, shapedirs, v_template);
    k0_pde<<<(KE * VPITCH) / 256, 256>>>(posedirs, shapedirs);
    k1_pose<<<BQ, 32>>>(betas, poses, out_joints);
    k2_gemm<<<dim3(VPITCH / 128, BQ / 128), 256>>>(v_template);
    k3_skin<<<dim3((VN + 255) / 256, BQ / NBPB), 256>>>(lbs_w, out_verts);
    k4_reg<<<BQ / K4B, 256>>>(Je9, Jh17, out_verts, out_joints);
    k5_gather<<<(BQ * 11 * 3) / 256, 256>>>(ext_idx, out_verts, out_joints);
}